// round 1
// baseline (speedup 1.0000x reference)
#include <cuda_runtime.h>
#include <math.h>

// Problem constants (hardcoded from reference)
#define BATCH   4
#define NTOK    4096
#define DMODEL  1024
#define NHEAD   16
#define HDIM    64
#define KANCH   256
#define MROWS   (BATCH * NTOK)        // 16384
#define SCALE   0.125f                // 1/sqrt(64)

// Scratch (device globals — allocation-free per harness rules)
__device__ float g_Q[MROWS * DMODEL];            // 64 MB: projected Q for all tokens
__device__ float g_K[BATCH * KANCH * DMODEL];    // 4 MB
__device__ float g_V[BATCH * KANCH * DMODEL];    // 4 MB
__device__ float g_ctx[MROWS * DMODEL];          // 64 MB: attention output (B,N,H*HD)

// ---------------------------------------------------------------------------
// Shared GEMM body: C[128x128 tile] = A(128 x 1024) @ W(1024 x 1024) + bias
// A row-major with row stride 1024, W row-major (1024 x 1024), C row stride 1024.
// 256 threads, 8x8 per-thread microtile, BK=8.
// ---------------------------------------------------------------------------
__device__ __forceinline__ void gemm_tile_1024(
    const float* __restrict__ Ab,     // base of this block's 128 rows
    const float* __restrict__ W,      // weight, row-major 1024x1024
    const float* __restrict__ bias,   // 1024
    float* __restrict__ Cb,           // base of this block's 128 output rows
    int bcol)                         // which 128-col tile of the 1024 output cols
{
    __shared__ float As[8][128];
    __shared__ float Bs[8][128];

    const int tid  = threadIdx.x;
    const int trow = tid >> 4;        // 0..15
    const int tcol = tid & 15;        // 0..15

    const int aRow = tid >> 1;        // 0..127
    const int aCol = (tid & 1) * 4;   // 0 or 4
    const int bRow = tid >> 5;        // 0..7
    const int bCol = (tid & 31) * 4;  // 0..124

    const float* Wb = W + bcol * 128;

    float acc[8][8];
#pragma unroll
    for (int i = 0; i < 8; i++)
#pragma unroll
        for (int j = 0; j < 8; j++) acc[i][j] = 0.f;

    for (int k0 = 0; k0 < DMODEL; k0 += 8) {
        float4 a4 = *reinterpret_cast<const float4*>(Ab + (size_t)aRow * DMODEL + k0 + aCol);
        As[aCol + 0][aRow] = a4.x;
        As[aCol + 1][aRow] = a4.y;
        As[aCol + 2][aRow] = a4.z;
        As[aCol + 3][aRow] = a4.w;
        float4 b4 = *reinterpret_cast<const float4*>(Wb + (size_t)(k0 + bRow) * DMODEL + bCol);
        *reinterpret_cast<float4*>(&Bs[bRow][bCol]) = b4;
        __syncthreads();

#pragma unroll
        for (int kk = 0; kk < 8; kk++) {
            float ra[8], rb[8];
#pragma unroll
            for (int i = 0; i < 8; i++) ra[i] = As[kk][trow * 8 + i];
#pragma unroll
            for (int j = 0; j < 8; j++) rb[j] = Bs[kk][tcol * 8 + j];
#pragma unroll
            for (int i = 0; i < 8; i++)
#pragma unroll
                for (int j = 0; j < 8; j++)
                    acc[i][j] = fmaf(ra[i], rb[j], acc[i][j]);
        }
        __syncthreads();
    }

#pragma unroll
    for (int i = 0; i < 8; i++) {
        const int row = trow * 8 + i;
#pragma unroll
        for (int j = 0; j < 8; j += 4) {
            const int col = bcol * 128 + tcol * 8 + j;
            float4 bv = *reinterpret_cast<const float4*>(bias + col);
            float4 o;
            o.x = acc[i][j + 0] + bv.x;
            o.y = acc[i][j + 1] + bv.y;
            o.z = acc[i][j + 2] + bv.z;
            o.w = acc[i][j + 3] + bv.w;
            *reinterpret_cast<float4*>(Cb + (size_t)row * DMODEL + col) = o;
        }
    }
}

// ---- Q projection: anchors use Wq/bq, queries use Wqt/bqt (per-block select) ----
__global__ void __launch_bounds__(256) qproj_kernel(
    const float* __restrict__ x,
    const float* __restrict__ Wq,  const float* __restrict__ bq,
    const float* __restrict__ Wqt, const float* __restrict__ bqt)
{
    const int brow = blockIdx.y;                  // 0..127 (16384 rows / 128)
    const int base = brow * 128;
    const bool anchor = (base % NTOK) < KANCH;    // 128-row tile is homogeneous
    const float* W = anchor ? Wq : Wqt;
    const float* b = anchor ? bq : bqt;
    gemm_tile_1024(x + (size_t)base * DMODEL, W, b,
                   g_Q + (size_t)base * DMODEL, blockIdx.x);
}

// ---- K/V projection over anchors (rows first 256 of each batch) ----
__global__ void __launch_bounds__(256) kvproj_kernel(
    const float* __restrict__ x,
    const float* __restrict__ Wk, const float* __restrict__ bk,
    const float* __restrict__ Wv, const float* __restrict__ bv)
{
    const int brow = blockIdx.y;                  // 0..7 (1024 anchor rows / 128)
    const int base = brow * 128;
    const int b    = base / KANCH;
    const int n0   = base % KANCH;
    const float* Ab = x + ((size_t)b * NTOK + n0) * DMODEL;
    if (blockIdx.z == 0)
        gemm_tile_1024(Ab, Wk, bk, g_K + (size_t)base * DMODEL, blockIdx.x);
    else
        gemm_tile_1024(Ab, Wv, bv, g_V + (size_t)base * DMODEL, blockIdx.x);
}

// ---- Output projection: ctx @ Wo + bo -> out ----
__global__ void __launch_bounds__(256) oproj_kernel(
    const float* __restrict__ Wo, const float* __restrict__ bo,
    float* __restrict__ out)
{
    const int base = blockIdx.y * 128;
    gemm_tile_1024(g_ctx + (size_t)base * DMODEL, Wo, bo,
                   out + (size_t)base * DMODEL, blockIdx.x);
}

// ---------------------------------------------------------------------------
// Fused attention: for each (b,h), scores = Q_tile @ K^T * SCALE, online
// softmax over 256 keys, ctx = P @ V. One query row per thread, 128 rows per
// block; K/V staged through smem in 64-key chunks (32 KB static smem).
// ---------------------------------------------------------------------------
__global__ void __launch_bounds__(128) attn_kernel()
{
    __shared__ float Ks[64 * 64];
    __shared__ float Vs[64 * 64];

    const int b = blockIdx.z;
    const int h = blockIdx.y;
    const int n = blockIdx.x * 128 + threadIdx.x;

    const float* qp = g_Q + ((size_t)(b * NTOK + n)) * DMODEL + h * HDIM;
    float4 qv[16];
#pragma unroll
    for (int i = 0; i < 16; i++)
        qv[i] = *reinterpret_cast<const float4*>(qp + i * 4);

    float m = -INFINITY;
    float l = 0.f;
    float acc[HDIM];
#pragma unroll
    for (int d = 0; d < HDIM; d++) acc[d] = 0.f;

    for (int jc = 0; jc < KANCH; jc += 64) {
        __syncthreads();
        const float* kg = g_K + ((size_t)(b * KANCH + jc)) * DMODEL + h * HDIM;
        const float* vg = g_V + ((size_t)(b * KANCH + jc)) * DMODEL + h * HDIM;
        for (int i = threadIdx.x; i < 64 * 16; i += 128) {
            const int j  = i >> 4;
            const int d4 = (i & 15) * 4;
            reinterpret_cast<float4*>(Ks)[i] =
                *reinterpret_cast<const float4*>(kg + (size_t)j * DMODEL + d4);
            reinterpret_cast<float4*>(Vs)[i] =
                *reinterpret_cast<const float4*>(vg + (size_t)j * DMODEL + d4);
        }
        __syncthreads();

        for (int j = 0; j < 64; j++) {
            const float4* kr = reinterpret_cast<const float4*>(Ks + j * HDIM);
            float s = 0.f;
#pragma unroll
            for (int i = 0; i < 16; i++) {
                float4 k4 = kr[i];
                s = fmaf(qv[i].x, k4.x, s);
                s = fmaf(qv[i].y, k4.y, s);
                s = fmaf(qv[i].z, k4.z, s);
                s = fmaf(qv[i].w, k4.w, s);
            }
            s *= SCALE;

            if (s > m) {
                const float corr = __expf(m - s);   // first iter: exp(-inf)=0
                l *= corr;
#pragma unroll
                for (int d = 0; d < HDIM; d++) acc[d] *= corr;
                m = s;
            }
            const float p = __expf(s - m);
            l += p;
            const float* vr = Vs + j * HDIM;
#pragma unroll
            for (int d = 0; d < HDIM; d++)
                acc[d] = fmaf(p, vr[d], acc[d]);
        }
    }

    const float inv = 1.f / l;
    float* op = g_ctx + ((size_t)(b * NTOK + n)) * DMODEL + h * HDIM;
#pragma unroll
    for (int d = 0; d < HDIM; d += 4) {
        float4 o;
        o.x = acc[d + 0] * inv;
        o.y = acc[d + 1] * inv;
        o.z = acc[d + 2] * inv;
        o.w = acc[d + 3] * inv;
        *reinterpret_cast<float4*>(op + d) = o;
    }
}

// ---------------------------------------------------------------------------
// kernel_launch: graph-capturable pipeline of 4 kernels
// ---------------------------------------------------------------------------
extern "C" void kernel_launch(void* const* d_in, const int* in_sizes, int n_in,
                              void* d_out, int out_size)
{
    const float* x   = (const float*)d_in[0];
    const float* Wq  = (const float*)d_in[1];
    const float* bq  = (const float*)d_in[2];
    const float* Wk  = (const float*)d_in[3];
    const float* bk  = (const float*)d_in[4];
    const float* Wv  = (const float*)d_in[5];
    const float* bv  = (const float*)d_in[6];
    const float* Wqt = (const float*)d_in[7];
    const float* bqt = (const float*)d_in[8];
    const float* Wo  = (const float*)d_in[9];
    const float* bo  = (const float*)d_in[10];
    float* out = (float*)d_out;

    // 1) Q projection for all 16384 token rows (per-block anchor/query select)
    qproj_kernel<<<dim3(DMODEL / 128, MROWS / 128), 256>>>(x, Wq, bq, Wqt, bqt);

    // 2) K and V projections over the 1024 anchor rows
    kvproj_kernel<<<dim3(DMODEL / 128, (BATCH * KANCH) / 128, 2), 256>>>(x, Wk, bk, Wv, bv);

    // 3) Fused attention (online softmax over 256 anchor keys)
    attn_kernel<<<dim3(NTOK / 128, NHEAD, BATCH), 128>>>();

    // 4) Output projection
    oproj_kernel<<<dim3(DMODEL / 128, MROWS / 128), 256>>>(Wo, bo, out);
}

// round 6
// speedup vs baseline: 2.5350x; 2.5350x over previous
#include <cuda_runtime.h>
#include <cuda_bf16.h>
#include <math.h>
#include <stdint.h>

// Problem constants
#define BATCH   4
#define NTOK    4096
#define DMODEL  1024
#define NHEAD   16
#define HDIM    64
#define KANCH   256
#define MROWS   (BATCH * NTOK)        // 16384
#define SCALE   0.125f

// ---------------------------------------------------------------------------
// Scratch (device globals — allocation-free per harness rules).
// RULE (round-5 post-mortem): device symbols are ONLY referenced from device
// code. Never passed as kernel arguments from host (host shadow + GB300 ATS
// silently swallows the stores).
// ---------------------------------------------------------------------------
__device__ float g_Q[MROWS * DMODEL];                 // 64 MB
__device__ float g_K[BATCH * KANCH * DMODEL];         // 4 MB
__device__ float g_V[BATCH * KANCH * DMODEL];         // 4 MB
__device__ __align__(16) __nv_bfloat16 g_xhi[MROWS * DMODEL];   // 32 MB
__device__ __align__(16) __nv_bfloat16 g_xlo[MROWS * DMODEL];
__device__ __align__(16) __nv_bfloat16 g_chi[MROWS * DMODEL];   // ctx hi/lo
__device__ __align__(16) __nv_bfloat16 g_clo[MROWS * DMODEL];
// Transposed+split weights: [N][K] K-major. 0=Wq 1=Wqt 2=Wk 3=Wv 4=Wo
__device__ __align__(16) __nv_bfloat16 g_Wh[5][DMODEL * DMODEL];
__device__ __align__(16) __nv_bfloat16 g_Wl[5][DMODEL * DMODEL];

// ---------------------------------------------------------------------------
// Warp-level bf16 MMA (sm_80+, fallback HMMA on sm_103)
// ---------------------------------------------------------------------------
__device__ __forceinline__ void mma_bf16(float* c, const uint32_t* a,
                                         uint32_t b0, uint32_t b1) {
    asm volatile(
        "mma.sync.aligned.m16n8k16.row.col.f32.bf16.bf16.f32 "
        "{%0,%1,%2,%3}, {%4,%5,%6,%7}, {%8,%9}, {%0,%1,%2,%3};"
        : "+f"(c[0]), "+f"(c[1]), "+f"(c[2]), "+f"(c[3])
        : "r"(a[0]), "r"(a[1]), "r"(a[2]), "r"(a[3]), "r"(b0), "r"(b1));
}

// ---------------------------------------------------------------------------
// bf16x3 GEMM: C[128x128] = A(128x1024) @ B^T(128x1024) + bias
// Plain padded row-major smem, scalar u32 fragment loads (PTX m16n8k16 lane
// mapping), 256 threads, 8 warps (4x2), warp tile 32x64, BK=32.
// ---------------------------------------------------------------------------
#define PADK      17
#define MAT_U32   (128 * PADK)                  // 2176 u32 per matrix
#define GEMM_SMEM (4 * MAT_U32 * 4)             // 34816 bytes

__device__ __forceinline__ void gemm_mma(
    const __nv_bfloat16* __restrict__ Ahi, const __nv_bfloat16* __restrict__ Alo,
    const __nv_bfloat16* __restrict__ Bhi, const __nv_bfloat16* __restrict__ Blo,
    const float* __restrict__ bias, float* __restrict__ Cb, int ldc)
{
    extern __shared__ uint32_t sm[];
    const int tid  = threadIdx.x;
    const int lane = tid & 31;
    const int wid  = tid >> 5;
    const int wm   = wid >> 1;       // 0..3 -> M offset wm*32
    const int wn   = wid & 1;        // 0..1 -> N offset wn*64
    const int g    = lane >> 2;      // 0..7
    const int t    = lane & 3;       // 0..3

    float acc[2][8][4];
#pragma unroll
    for (int i = 0; i < 2; i++)
#pragma unroll
        for (int j = 0; j < 8; j++)
#pragma unroll
            for (int k = 0; k < 4; k++) acc[i][j][k] = 0.f;

    const uint4* gp[4] = { (const uint4*)Ahi, (const uint4*)Alo,
                           (const uint4*)Bhi, (const uint4*)Blo };

    const int r0  = tid >> 2;        // 0..63 (row; also handles r0+64)
    const int ch0 = tid & 3;         // 16B chunk (4 u32) within the 64B K-slice

    for (int c = 0; c < 32; c++) {   // 32 K-chunks of 32 bf16
        __syncthreads();             // previous compute done before overwrite
        const size_t gq = (size_t)c * 4 + ch0;   // uint4 col within 128-uint4 row
#pragma unroll
        for (int m = 0; m < 4; m++) {
            uint4 v0 = gp[m][(size_t)r0 * 128 + gq];
            uint4 v1 = gp[m][(size_t)(r0 + 64) * 128 + gq];
            uint32_t* s0 = sm + m * MAT_U32 + r0 * PADK + ch0 * 4;
            uint32_t* s1 = sm + m * MAT_U32 + (r0 + 64) * PADK + ch0 * 4;
            s0[0] = v0.x; s0[1] = v0.y; s0[2] = v0.z; s0[3] = v0.w;
            s1[0] = v1.x; s1[1] = v1.y; s1[2] = v1.z; s1[3] = v1.w;
        }
        __syncthreads();             // tile visible to all warps

#pragma unroll
        for (int ks = 0; ks < 2; ks++) {
            const int kb = ks * 8;   // u32 col base (16 bf16 per mma K)
            uint32_t aHi[2][4], aLo[2][4];
#pragma unroll
            for (int mf = 0; mf < 2; mf++) {
                const int ra = (wm * 32 + mf * 16 + g) * PADK + kb + t;
                aHi[mf][0] = sm[ra];
                aHi[mf][1] = sm[ra + 8 * PADK];
                aHi[mf][2] = sm[ra + 4];
                aHi[mf][3] = sm[ra + 8 * PADK + 4];
                aLo[mf][0] = sm[MAT_U32 + ra];
                aLo[mf][1] = sm[MAT_U32 + ra + 8 * PADK];
                aLo[mf][2] = sm[MAT_U32 + ra + 4];
                aLo[mf][3] = sm[MAT_U32 + ra + 8 * PADK + 4];
            }
#pragma unroll
            for (int nq = 0; nq < 4; nq++) {
#pragma unroll
                for (int hf = 0; hf < 2; hf++) {
                    const int rb = (wn * 64 + nq * 16 + hf * 8 + g) * PADK + kb + t;
                    const uint32_t b0h = sm[2 * MAT_U32 + rb];
                    const uint32_t b1h = sm[2 * MAT_U32 + rb + 4];
                    const uint32_t b0l = sm[3 * MAT_U32 + rb];
                    const uint32_t b1l = sm[3 * MAT_U32 + rb + 4];
                    float* c0 = acc[0][nq * 2 + hf];
                    float* c1 = acc[1][nq * 2 + hf];
                    mma_bf16(c0, aHi[0], b0h, b1h);
                    mma_bf16(c0, aHi[0], b0l, b1l);
                    mma_bf16(c0, aLo[0], b0h, b1h);
                    mma_bf16(c1, aHi[1], b0h, b1h);
                    mma_bf16(c1, aHi[1], b0l, b1l);
                    mma_bf16(c1, aLo[1], b0h, b1h);
                }
            }
        }
    }

    // Epilogue: add bias, store fp32
#pragma unroll
    for (int mf = 0; mf < 2; mf++) {
#pragma unroll
        for (int nf = 0; nf < 8; nf++) {
            const int row = wm * 32 + mf * 16 + g;
            const int col = wn * 64 + nf * 8 + t * 2;
            const float bx = bias[col], by = bias[col + 1];
            float2 v0 = { acc[mf][nf][0] + bx, acc[mf][nf][1] + by };
            float2 v1 = { acc[mf][nf][2] + bx, acc[mf][nf][3] + by };
            *reinterpret_cast<float2*>(Cb + (size_t)row * ldc + col) = v0;
            *reinterpret_cast<float2*>(Cb + (size_t)(row + 8) * ldc + col) = v1;
        }
    }
}

// ---- Q projection (anchor rows use Wq/bq, query rows Wqt/bqt) ----
__global__ void __launch_bounds__(256) qproj_kernel(
    const float* __restrict__ bq, const float* __restrict__ bqt)
{
    const int Mb = blockIdx.y * 128;
    const int Nb = blockIdx.x * 128;
    const bool anchor = (Mb % NTOK) < KANCH;
    const int w = anchor ? 0 : 1;
    gemm_mma(g_xhi + (size_t)Mb * DMODEL, g_xlo + (size_t)Mb * DMODEL,
             g_Wh[w] + (size_t)Nb * DMODEL, g_Wl[w] + (size_t)Nb * DMODEL,
             (anchor ? bq : bqt) + Nb,
             g_Q + (size_t)Mb * DMODEL + Nb, DMODEL);
}

// ---- K/V projection over the 1024 anchor rows ----
__global__ void __launch_bounds__(256) kvproj_kernel(
    const float* __restrict__ bk, const float* __restrict__ bv)
{
    const int Mt = blockIdx.y;                          // 0..7
    const int arow = (Mt >> 1) * NTOK + (Mt & 1) * 128; // anchor row in x
    const int Nb = blockIdx.x * 128;
    const int w = (blockIdx.z == 0) ? 2 : 3;
    float* outb = ((blockIdx.z == 0) ? g_K : g_V) + (size_t)Mt * 128 * DMODEL + Nb;
    gemm_mma(g_xhi + (size_t)arow * DMODEL, g_xlo + (size_t)arow * DMODEL,
             g_Wh[w] + (size_t)Nb * DMODEL, g_Wl[w] + (size_t)Nb * DMODEL,
             (blockIdx.z == 0 ? bk : bv) + Nb, outb, DMODEL);
}

// ---- Output projection: ctx(hi/lo) @ Wo + bo -> out ----
__global__ void __launch_bounds__(256) oproj_kernel(
    const float* __restrict__ bo, float* __restrict__ out)
{
    const int Mb = blockIdx.y * 128;
    const int Nb = blockIdx.x * 128;
    gemm_mma(g_chi + (size_t)Mb * DMODEL, g_clo + (size_t)Mb * DMODEL,
             g_Wh[4] + (size_t)Nb * DMODEL, g_Wl[4] + (size_t)Nb * DMODEL,
             bo + Nb, out + (size_t)Mb * DMODEL + Nb, DMODEL);
}

// ---------------------------------------------------------------------------
// Split x fp32 -> (g_xhi, g_xlo). Outputs referenced as DEVICE symbols only.
// ---------------------------------------------------------------------------
__global__ void __launch_bounds__(256) split_x_kernel(const float* __restrict__ in)
{
    const int n4 = MROWS * DMODEL / 4;
    for (int i = blockIdx.x * blockDim.x + threadIdx.x; i < n4; i += gridDim.x * blockDim.x) {
        float4 v = reinterpret_cast<const float4*>(in)[i];
        __nv_bfloat16 h0 = __float2bfloat16(v.x), h1 = __float2bfloat16(v.y);
        __nv_bfloat16 h2 = __float2bfloat16(v.z), h3 = __float2bfloat16(v.w);
        __nv_bfloat162 hA, hB, lA, lB;
        hA.x = h0; hA.y = h1; hB.x = h2; hB.y = h3;
        lA.x = __float2bfloat16(v.x - __bfloat162float(h0));
        lA.y = __float2bfloat16(v.y - __bfloat162float(h1));
        lB.x = __float2bfloat16(v.z - __bfloat162float(h2));
        lB.y = __float2bfloat16(v.w - __bfloat162float(h3));
        reinterpret_cast<__nv_bfloat162*>(g_xhi)[i * 2 + 0] = hA;
        reinterpret_cast<__nv_bfloat162*>(g_xhi)[i * 2 + 1] = hB;
        reinterpret_cast<__nv_bfloat162*>(g_xlo)[i * 2 + 0] = lA;
        reinterpret_cast<__nv_bfloat162*>(g_xlo)[i * 2 + 1] = lB;
    }
}

// ---------------------------------------------------------------------------
// Transpose + split weights: src [K][N] row-major -> g_Wh/g_Wl [N][K] hi/lo
// (outputs referenced as device symbols only — this was always correct)
// ---------------------------------------------------------------------------
__global__ void __launch_bounds__(256) wprep_kernel(
    const float* __restrict__ Wq, const float* __restrict__ Wqt,
    const float* __restrict__ Wk, const float* __restrict__ Wv,
    const float* __restrict__ Wo)
{
    __shared__ float t[32][33];
    const float* src;
    switch (blockIdx.z) {
        case 0: src = Wq;  break;
        case 1: src = Wqt; break;
        case 2: src = Wk;  break;
        case 3: src = Wv;  break;
        default: src = Wo; break;
    }
    __nv_bfloat16* dh = g_Wh[blockIdx.z];
    __nv_bfloat16* dl = g_Wl[blockIdx.z];
    const int n0 = blockIdx.x * 32, k0 = blockIdx.y * 32;
    for (int i = threadIdx.y; i < 32; i += 8)
        t[i][threadIdx.x] = src[(size_t)(k0 + i) * DMODEL + n0 + threadIdx.x];
    __syncthreads();
    for (int i = threadIdx.y; i < 32; i += 8) {
        float v = t[threadIdx.x][i];
        __nv_bfloat16 h = __float2bfloat16(v);
        size_t idx = (size_t)(n0 + i) * DMODEL + k0 + threadIdx.x;
        dh[idx] = h;
        dl[idx] = __float2bfloat16(v - __bfloat162float(h));
    }
}

// ---------------------------------------------------------------------------
// Fused attention (fp32 SIMT): online softmax over 256 anchor keys.
// Writes ctx directly as bf16 hi/lo (device symbols).
// ---------------------------------------------------------------------------
__global__ void __launch_bounds__(128) attn_kernel()
{
    __shared__ float Ks[64 * 64];
    __shared__ float Vs[64 * 64];

    const int b = blockIdx.z;
    const int h = blockIdx.y;
    const int n = blockIdx.x * 128 + threadIdx.x;

    const float* qp = g_Q + ((size_t)(b * NTOK + n)) * DMODEL + h * HDIM;
    float4 qv[16];
#pragma unroll
    for (int i = 0; i < 16; i++)
        qv[i] = *reinterpret_cast<const float4*>(qp + i * 4);

    float m = -INFINITY;
    float l = 0.f;
    float acc[HDIM];
#pragma unroll
    for (int d = 0; d < HDIM; d++) acc[d] = 0.f;

    for (int jc = 0; jc < KANCH; jc += 64) {
        __syncthreads();
        const float* kg = g_K + ((size_t)(b * KANCH + jc)) * DMODEL + h * HDIM;
        const float* vg = g_V + ((size_t)(b * KANCH + jc)) * DMODEL + h * HDIM;
        for (int i = threadIdx.x; i < 64 * 16; i += 128) {
            const int j  = i >> 4;
            const int d4 = (i & 15) * 4;
            reinterpret_cast<float4*>(Ks)[i] =
                *reinterpret_cast<const float4*>(kg + (size_t)j * DMODEL + d4);
            reinterpret_cast<float4*>(Vs)[i] =
                *reinterpret_cast<const float4*>(vg + (size_t)j * DMODEL + d4);
        }
        __syncthreads();

        for (int j = 0; j < 64; j++) {
            const float4* kr = reinterpret_cast<const float4*>(Ks + j * HDIM);
            float s = 0.f;
#pragma unroll
            for (int i = 0; i < 16; i++) {
                float4 k4 = kr[i];
                s = fmaf(qv[i].x, k4.x, s);
                s = fmaf(qv[i].y, k4.y, s);
                s = fmaf(qv[i].z, k4.z, s);
                s = fmaf(qv[i].w, k4.w, s);
            }
            s *= SCALE;
            if (s > m) {
                const float corr = __expf(m - s);
                l *= corr;
#pragma unroll
                for (int d = 0; d < HDIM; d++) acc[d] *= corr;
                m = s;
            }
            const float p = __expf(s - m);
            l += p;
            const float* vr = Vs + j * HDIM;
#pragma unroll
            for (int d = 0; d < HDIM; d++)
                acc[d] = fmaf(p, vr[d], acc[d]);
        }
    }

    const float inv = 1.f / l;
    const size_t idx = ((size_t)(b * NTOK + n)) * DMODEL + h * HDIM;
#pragma unroll
    for (int d = 0; d < HDIM; d += 2) {
        float v0 = acc[d + 0] * inv;
        float v1 = acc[d + 1] * inv;
        __nv_bfloat162 hh, ll;
        hh.x = __float2bfloat16(v0);
        hh.y = __float2bfloat16(v1);
        ll.x = __float2bfloat16(v0 - __bfloat162float(hh.x));
        ll.y = __float2bfloat16(v1 - __bfloat162float(hh.y));
        *reinterpret_cast<__nv_bfloat162*>(g_chi + idx + d) = hh;
        *reinterpret_cast<__nv_bfloat162*>(g_clo + idx + d) = ll;
    }
}

// ---------------------------------------------------------------------------
// kernel_launch: graph-capturable pipeline (dynamic smem 34816 B, no opt-in).
// No device symbols passed as arguments — only harness pointers.
// ---------------------------------------------------------------------------
extern "C" void kernel_launch(void* const* d_in, const int* in_sizes, int n_in,
                              void* d_out, int out_size)
{
    const float* x   = (const float*)d_in[0];
    const float* Wq  = (const float*)d_in[1];
    const float* bq  = (const float*)d_in[2];
    const float* Wk  = (const float*)d_in[3];
    const float* bk  = (const float*)d_in[4];
    const float* Wv  = (const float*)d_in[5];
    const float* bv  = (const float*)d_in[6];
    const float* Wqt = (const float*)d_in[7];
    const float* bqt = (const float*)d_in[8];
    const float* Wo  = (const float*)d_in[9];
    const float* bo  = (const float*)d_in[10];
    float* out = (float*)d_out;

    // 1) split x into bf16 hi/lo (device-symbol outputs)
    split_x_kernel<<<4096, 256>>>(x);

    // 2) transpose+split all 5 weight matrices
    wprep_kernel<<<dim3(32, 32, 5), dim3(32, 8)>>>(Wq, Wqt, Wk, Wv, Wo);

    // 3) projections on tensor cores (bf16x3 mma.sync)
    qproj_kernel<<<dim3(8, 128), 256, GEMM_SMEM>>>(bq, bqt);
    kvproj_kernel<<<dim3(8, 8, 2), 256, GEMM_SMEM>>>(bk, bv);

    // 4) fused attention (writes ctx hi/lo directly)
    attn_kernel<<<dim3(NTOK / 128, NHEAD, BATCH), 128>>>();

    // 5) output projection
    oproj_kernel<<<dim3(8, 128), 256, GEMM_SMEM>>>(bo, out);
}

// round 7
// speedup vs baseline: 4.1755x; 1.6472x over previous
#include <cuda_runtime.h>
#include <cuda_bf16.h>
#include <math.h>
#include <stdint.h>

// Problem constants
#define BATCH   4
#define NTOK    4096
#define DMODEL  1024
#define NHEAD   16
#define HDIM    64
#define KANCH   256
#define MROWS   (BATCH * NTOK)        // 16384
#define SCALE   0.125f

// ---------------------------------------------------------------------------
// Scratch (device globals). RULE: device symbols referenced ONLY from device
// code (host-shadow + GB300 ATS silently swallows host-passed symbol stores).
// ---------------------------------------------------------------------------
__device__ __align__(16) __nv_bfloat16 g_xhi[MROWS * DMODEL];
__device__ __align__(16) __nv_bfloat16 g_xlo[MROWS * DMODEL];
__device__ __align__(16) __nv_bfloat16 g_Qhi[MROWS * DMODEL];
__device__ __align__(16) __nv_bfloat16 g_Qlo[MROWS * DMODEL];
__device__ __align__(16) __nv_bfloat16 g_Khi[BATCH * KANCH * DMODEL];
__device__ __align__(16) __nv_bfloat16 g_Klo[BATCH * KANCH * DMODEL];
// V transposed per (b,h): [b][h][d][key]
__device__ __align__(16) __nv_bfloat16 g_Vthi[BATCH * NHEAD * HDIM * KANCH];
__device__ __align__(16) __nv_bfloat16 g_Vtlo[BATCH * NHEAD * HDIM * KANCH];
__device__ __align__(16) __nv_bfloat16 g_chi[MROWS * DMODEL];
__device__ __align__(16) __nv_bfloat16 g_clo[MROWS * DMODEL];
// Transposed+split weights: [N][K] K-major. 0=Wq 1=Wqt 2=Wk 3=Wv 4=Wo
__device__ __align__(16) __nv_bfloat16 g_Wh[5][DMODEL * DMODEL];
__device__ __align__(16) __nv_bfloat16 g_Wl[5][DMODEL * DMODEL];

// ---------------------------------------------------------------------------
// Primitives
// ---------------------------------------------------------------------------
__device__ __forceinline__ uint32_t smem_to_u32(const void* p) {
    uint32_t a;
    asm("{ .reg .u64 t; cvta.to.shared.u64 t, %1; cvt.u32.u64 %0, t; }" : "=r"(a) : "l"(p));
    return a;
}
#define CP16(d, s) \
    asm volatile("cp.async.cg.shared.global [%0], [%1], 16;" :: "r"(d), "l"(s))
#define CP_COMMIT() asm volatile("cp.async.commit_group;")

__device__ __forceinline__ void mma_bf16(float* c, const uint32_t* a,
                                         uint32_t b0, uint32_t b1) {
    asm volatile(
        "mma.sync.aligned.m16n8k16.row.col.f32.bf16.bf16.f32 "
        "{%0,%1,%2,%3}, {%4,%5,%6,%7}, {%8,%9}, {%0,%1,%2,%3};"
        : "+f"(c[0]), "+f"(c[1]), "+f"(c[2]), "+f"(c[3])
        : "r"(a[0]), "r"(a[1]), "r"(a[2]), "r"(a[3]), "r"(b0), "r"(b1));
}

__device__ __forceinline__ uint32_t pack_bf16x2(float v0, float v1) {
    __nv_bfloat162 h; h.x = __float2bfloat16(v0); h.y = __float2bfloat16(v1);
    return *reinterpret_cast<uint32_t*>(&h);
}
__device__ __forceinline__ void split2(float v0, float v1, uint32_t& hi, uint32_t& lo) {
    __nv_bfloat16 h0 = __float2bfloat16(v0), h1 = __float2bfloat16(v1);
    __nv_bfloat162 hh; hh.x = h0; hh.y = h1;
    __nv_bfloat162 ll;
    ll.x = __float2bfloat16(v0 - __bfloat162float(h0));
    ll.y = __float2bfloat16(v1 - __bfloat162float(h1));
    hi = *reinterpret_cast<uint32_t*>(&hh);
    lo = *reinterpret_cast<uint32_t*>(&ll);
}

// 16B-chunk XOR swizzle on 32B rows (8 u32): conflict-free frag loads,
// 16B-aligned cp.async stores.  (row, ch∈{0,1}) -> u32 offset.
#define SWADDR(row, ch) ((((row) << 3)) + ((((ch) ^ (((row) >> 2) & 1))) << 2))

// ---------------------------------------------------------------------------
// bf16x3 GEMM mainloop: acc = A(128x1024) @ B^T(128x1024)
// 256 thr, 8 warps (4x2), warp tile 32x64, BK=16, 2-stage cp.async.
// smem: 2 stages x 4 mats x 128 rows x 8 u32 = 32 KB dynamic.
// ---------------------------------------------------------------------------
#define GEMM_SMEM 32768

__device__ __forceinline__ void gemm_main(
    const __nv_bfloat16* __restrict__ Ahi, const __nv_bfloat16* __restrict__ Alo,
    const __nv_bfloat16* __restrict__ Bhi, const __nv_bfloat16* __restrict__ Blo,
    float acc[2][8][4])
{
    extern __shared__ uint32_t sm[];
    const int tid  = threadIdx.x;
    const int lane = tid & 31;
    const int wid  = tid >> 5;
    const int wm   = wid >> 1;
    const int wn   = wid & 1;
    const int g    = lane >> 2;
    const int t    = lane & 3;

#pragma unroll
    for (int i = 0; i < 2; i++)
#pragma unroll
        for (int j = 0; j < 8; j++)
#pragma unroll
            for (int k = 0; k < 4; k++) acc[i][j][k] = 0.f;

    const char* gp[4] = { (const char*)Ahi, (const char*)Alo,
                          (const char*)Bhi, (const char*)Blo };

    const int row = tid >> 1;
    const int ch  = tid & 1;
    const uint32_t swo = SWADDR(row, ch);               // u32 offset in mat
    const uint32_t sb  = smem_to_u32(sm);
    const size_t   gof = (size_t)row * 512 + ch * 4;    // u32 offset in gmem row

#define G_ISSUE(c) do {                                                        \
        const uint32_t _st = ((uint32_t)((c) & 1)) * 4096u;                    \
        const size_t _gb = (gof + (size_t)(c) * 8) << 2;                       \
        _Pragma("unroll")                                                      \
        for (int m = 0; m < 4; m++)                                            \
            CP16(sb + ((_st + m * 1024u + swo) << 2), gp[m] + _gb);            \
        CP_COMMIT();                                                           \
    } while (0)

    G_ISSUE(0);

    for (int c = 0; c < 64; c++) {
        if (c + 1 < 64) { G_ISSUE(c + 1); asm volatile("cp.async.wait_group 1;"); }
        else            { asm volatile("cp.async.wait_group 0;"); }
        __syncthreads();

        const uint32_t* st = sm + (c & 1) * 4096;
        uint32_t aHi[2][4], aLo[2][4];
#pragma unroll
        for (int mf = 0; mf < 2; mf++) {
            const int rA0 = wm * 32 + mf * 16 + g;
            const int rA1 = rA0 + 8;
            aHi[mf][0] = st[SWADDR(rA0, 0) + t];
            aHi[mf][1] = st[SWADDR(rA1, 0) + t];
            aHi[mf][2] = st[SWADDR(rA0, 1) + t];
            aHi[mf][3] = st[SWADDR(rA1, 1) + t];
            aLo[mf][0] = st[1024 + SWADDR(rA0, 0) + t];
            aLo[mf][1] = st[1024 + SWADDR(rA1, 0) + t];
            aLo[mf][2] = st[1024 + SWADDR(rA0, 1) + t];
            aLo[mf][3] = st[1024 + SWADDR(rA1, 1) + t];
        }
#pragma unroll
        for (int nq = 0; nq < 4; nq++) {
#pragma unroll
            for (int hf = 0; hf < 2; hf++) {
                const int rB = wn * 64 + nq * 16 + hf * 8 + g;
                const uint32_t b0h = st[2048 + SWADDR(rB, 0) + t];
                const uint32_t b1h = st[2048 + SWADDR(rB, 1) + t];
                const uint32_t b0l = st[3072 + SWADDR(rB, 0) + t];
                const uint32_t b1l = st[3072 + SWADDR(rB, 1) + t];
                float* c0 = acc[0][nq * 2 + hf];
                float* c1 = acc[1][nq * 2 + hf];
                mma_bf16(c0, aHi[0], b0h, b1h);
                mma_bf16(c0, aHi[0], b0l, b1l);
                mma_bf16(c0, aLo[0], b0h, b1h);
                mma_bf16(c1, aHi[1], b0h, b1h);
                mma_bf16(c1, aHi[1], b0l, b1l);
                mma_bf16(c1, aLo[1], b0h, b1h);
            }
        }
        __syncthreads();
    }
#undef G_ISSUE
}

// ---- Q projection: writes bf16 hi/lo directly ----
__global__ void __launch_bounds__(256) qproj_kernel(
    const float* __restrict__ bq, const float* __restrict__ bqt)
{
    const int Mb = blockIdx.y * 128;
    const int Nb = blockIdx.x * 128;
    const bool anchor = (Mb % NTOK) < KANCH;
    const int w = anchor ? 0 : 1;
    float acc[2][8][4];
    gemm_main(g_xhi + (size_t)Mb * DMODEL, g_xlo + (size_t)Mb * DMODEL,
              g_Wh[w] + (size_t)Nb * DMODEL, g_Wl[w] + (size_t)Nb * DMODEL, acc);
    const float* bias = anchor ? bq : bqt;
    const int lane = threadIdx.x & 31, wid = threadIdx.x >> 5;
    const int wm = wid >> 1, wn = wid & 1, g = lane >> 2, t = lane & 3;
    uint32_t* Hi = (uint32_t*)g_Qhi;
    uint32_t* Lo = (uint32_t*)g_Qlo;
#pragma unroll
    for (int mf = 0; mf < 2; mf++)
#pragma unroll
        for (int nf = 0; nf < 8; nf++) {
            const int row = Mb + wm * 32 + mf * 16 + g;
            const int col = Nb + wn * 64 + nf * 8 + t * 2;
            const float bx = bias[col], by = bias[col + 1];
            uint32_t h0, l0, h1, l1;
            split2(acc[mf][nf][0] + bx, acc[mf][nf][1] + by, h0, l0);
            split2(acc[mf][nf][2] + bx, acc[mf][nf][3] + by, h1, l1);
            Hi[(size_t)row * 512 + col / 2] = h0;
            Lo[(size_t)row * 512 + col / 2] = l0;
            Hi[(size_t)(row + 8) * 512 + col / 2] = h1;
            Lo[(size_t)(row + 8) * 512 + col / 2] = l1;
        }
}

// ---- K projection over the 1024 anchor rows: bf16 hi/lo ----
__global__ void __launch_bounds__(256) kproj_kernel(const float* __restrict__ bk)
{
    const int Mt = blockIdx.y;
    const int arow = (Mt >> 1) * NTOK + (Mt & 1) * 128;
    const int Nb = blockIdx.x * 128;
    float acc[2][8][4];
    gemm_main(g_xhi + (size_t)arow * DMODEL, g_xlo + (size_t)arow * DMODEL,
              g_Wh[2] + (size_t)Nb * DMODEL, g_Wl[2] + (size_t)Nb * DMODEL, acc);
    const int lane = threadIdx.x & 31, wid = threadIdx.x >> 5;
    const int wm = wid >> 1, wn = wid & 1, g = lane >> 2, t = lane & 3;
    uint32_t* Hi = (uint32_t*)g_Khi;
    uint32_t* Lo = (uint32_t*)g_Klo;
#pragma unroll
    for (int mf = 0; mf < 2; mf++)
#pragma unroll
        for (int nf = 0; nf < 8; nf++) {
            const int row = Mt * 128 + wm * 32 + mf * 16 + g;   // anchor-row index
            const int col = Nb + wn * 64 + nf * 8 + t * 2;
            const float bx = bk[col], by = bk[col + 1];
            uint32_t h0, l0, h1, l1;
            split2(acc[mf][nf][0] + bx, acc[mf][nf][1] + by, h0, l0);
            split2(acc[mf][nf][2] + bx, acc[mf][nf][3] + by, h1, l1);
            Hi[(size_t)row * 512 + col / 2] = h0;
            Lo[(size_t)row * 512 + col / 2] = l0;
            Hi[(size_t)(row + 8) * 512 + col / 2] = h1;
            Lo[(size_t)(row + 8) * 512 + col / 2] = l1;
        }
}

// ---- V projection: writes TRANSPOSED bf16 hi/lo: g_Vt[b][h][d][key] ----
__global__ void __launch_bounds__(256) vproj_kernel(const float* __restrict__ bv)
{
    const int Mt = blockIdx.y;
    const int arow = (Mt >> 1) * NTOK + (Mt & 1) * 128;
    const int Nb = blockIdx.x * 128;
    float acc[2][8][4];
    gemm_main(g_xhi + (size_t)arow * DMODEL, g_xlo + (size_t)arow * DMODEL,
              g_Wh[3] + (size_t)Nb * DMODEL, g_Wl[3] + (size_t)Nb * DMODEL, acc);
    const int lane = threadIdx.x & 31, wid = threadIdx.x >> 5;
    const int wm = wid >> 1, wn = wid & 1, g = lane >> 2, t = lane & 3;
#pragma unroll
    for (int mf = 0; mf < 2; mf++)
#pragma unroll
        for (int nf = 0; nf < 8; nf++) {
            const int col = Nb + wn * 64 + nf * 8 + t * 2;
            const int h = col >> 6, d = col & 63;
#pragma unroll
            for (int rr = 0; rr < 2; rr++) {
                const int a = Mt * 128 + wm * 32 + mf * 16 + g + rr * 8;
                const int b = a >> 8, tok = a & 255;
                const float v0 = acc[mf][nf][rr * 2 + 0] + bv[col];
                const float v1 = acc[mf][nf][rr * 2 + 1] + bv[col + 1];
                const size_t i0 = ((size_t)((b * NHEAD + h) * HDIM + d)) * KANCH + tok;
                __nv_bfloat16 h0 = __float2bfloat16(v0);
                __nv_bfloat16 h1 = __float2bfloat16(v1);
                g_Vthi[i0] = h0;
                g_Vtlo[i0] = __float2bfloat16(v0 - __bfloat162float(h0));
                g_Vthi[i0 + KANCH] = h1;
                g_Vtlo[i0 + KANCH] = __float2bfloat16(v1 - __bfloat162float(h1));
            }
        }
}

// ---- Output projection: ctx(hi/lo) @ Wo + bo -> fp32 out ----
__global__ void __launch_bounds__(256) oproj_kernel(
    const float* __restrict__ bo, float* __restrict__ out)
{
    const int Mb = blockIdx.y * 128;
    const int Nb = blockIdx.x * 128;
    float acc[2][8][4];
    gemm_main(g_chi + (size_t)Mb * DMODEL, g_clo + (size_t)Mb * DMODEL,
              g_Wh[4] + (size_t)Nb * DMODEL, g_Wl[4] + (size_t)Nb * DMODEL, acc);
    const int lane = threadIdx.x & 31, wid = threadIdx.x >> 5;
    const int wm = wid >> 1, wn = wid & 1, g = lane >> 2, t = lane & 3;
#pragma unroll
    for (int mf = 0; mf < 2; mf++)
#pragma unroll
        for (int nf = 0; nf < 8; nf++) {
            const int row = Mb + wm * 32 + mf * 16 + g;
            const int col = Nb + wn * 64 + nf * 8 + t * 2;
            const float bx = bo[col], by = bo[col + 1];
            float2 v0 = { acc[mf][nf][0] + bx, acc[mf][nf][1] + by };
            float2 v1 = { acc[mf][nf][2] + bx, acc[mf][nf][3] + by };
            *reinterpret_cast<float2*>(out + (size_t)row * DMODEL + col) = v0;
            *reinterpret_cast<float2*>(out + (size_t)(row + 8) * DMODEL + col) = v1;
        }
}

// ---------------------------------------------------------------------------
// Split x fp32 -> g_xhi/g_xlo (device symbols only)
// ---------------------------------------------------------------------------
__global__ void __launch_bounds__(256) split_x_kernel(const float* __restrict__ in)
{
    const int n4 = MROWS * DMODEL / 4;
    for (int i = blockIdx.x * blockDim.x + threadIdx.x; i < n4; i += gridDim.x * blockDim.x) {
        float4 v = reinterpret_cast<const float4*>(in)[i];
        uint32_t hA, lA, hB, lB;
        split2(v.x, v.y, hA, lA);
        split2(v.z, v.w, hB, lB);
        reinterpret_cast<uint32_t*>(g_xhi)[i * 2 + 0] = hA;
        reinterpret_cast<uint32_t*>(g_xhi)[i * 2 + 1] = hB;
        reinterpret_cast<uint32_t*>(g_xlo)[i * 2 + 0] = lA;
        reinterpret_cast<uint32_t*>(g_xlo)[i * 2 + 1] = lB;
    }
}

// ---------------------------------------------------------------------------
// Transpose + split weights: src [K][N] -> g_Wh/g_Wl [N][K]
// ---------------------------------------------------------------------------
__global__ void __launch_bounds__(256) wprep_kernel(
    const float* __restrict__ Wq, const float* __restrict__ Wqt,
    const float* __restrict__ Wk, const float* __restrict__ Wv,
    const float* __restrict__ Wo)
{
    __shared__ float tbuf[32][33];
    const float* src;
    switch (blockIdx.z) {
        case 0: src = Wq;  break;
        case 1: src = Wqt; break;
        case 2: src = Wk;  break;
        case 3: src = Wv;  break;
        default: src = Wo; break;
    }
    __nv_bfloat16* dh = g_Wh[blockIdx.z];
    __nv_bfloat16* dl = g_Wl[blockIdx.z];
    const int n0 = blockIdx.x * 32, k0 = blockIdx.y * 32;
    for (int i = threadIdx.y; i < 32; i += 8)
        tbuf[i][threadIdx.x] = src[(size_t)(k0 + i) * DMODEL + n0 + threadIdx.x];
    __syncthreads();
    for (int i = threadIdx.y; i < 32; i += 8) {
        float v = tbuf[threadIdx.x][i];
        __nv_bfloat16 h = __float2bfloat16(v);
        size_t idx = (size_t)(n0 + i) * DMODEL + k0 + threadIdx.x;
        dh[idx] = h;
        dl[idx] = __float2bfloat16(v - __bfloat162float(h));
    }
}

// ---------------------------------------------------------------------------
// Tensor-core attention: CTA = 128 Q rows x one (b,h). 8 warps, warp = 16 rows.
// S[16x256] in accum regs (bf16x3 Q·K), full softmax (K=256, one pass),
// P·V with register-resident P hi/lo (bf16x3). Writes ctx hi/lo.
// ---------------------------------------------------------------------------
__global__ void __launch_bounds__(256) attn_mma_kernel()
{
    __shared__ uint32_t qsh[128 * 36], qsl[128 * 36];   // Q tile, stride 36
    __shared__ uint32_t kvh[1280], kvl[1280];           // K chunk (36) / V chunk (20)

    const int b = blockIdx.z, h = blockIdx.y;
    const int n0 = blockIdx.x * 128;
    const int tid = threadIdx.x, lane = tid & 31, wid = tid >> 5;
    const int g = lane >> 2, t = lane & 3;
    const int wr = wid * 16;

    // Q tile: 128 rows x 64d, hi+lo (2048 uint4)
    {
        const uint4* sH = (const uint4*)g_Qhi;
        const uint4* sL = (const uint4*)g_Qlo;
#pragma unroll
        for (int i = tid; i < 2048; i += 256) {
            const int mat = i >> 10, rr = (i & 1023) >> 3, q4 = i & 7;
            const size_t gi = (size_t)(b * NTOK + n0 + rr) * 128 + h * 8 + q4;
            uint4 v = mat ? sL[gi] : sH[gi];
            uint32_t* d = (mat ? qsl : qsh) + rr * 36 + q4 * 4;
            d[0] = v.x; d[1] = v.y; d[2] = v.z; d[3] = v.w;
        }
    }
    __syncthreads();

    // Persistent Q fragments
    uint32_t qh[4][4], ql[4][4];
#pragma unroll
    for (int ks = 0; ks < 4; ks++) {
        const int rA0 = (wr + g) * 36 + ks * 8 + t;
        const int rA1 = (wr + 8 + g) * 36 + ks * 8 + t;
        qh[ks][0] = qsh[rA0]; qh[ks][1] = qsh[rA1];
        qh[ks][2] = qsh[rA0 + 4]; qh[ks][3] = qsh[rA1 + 4];
        ql[ks][0] = qsl[rA0]; ql[ks][1] = qsl[rA1];
        ql[ks][2] = qsl[rA0 + 4]; ql[ks][3] = qsl[rA1 + 4];
    }

    float s[32][4];
#pragma unroll
    for (int i = 0; i < 32; i++)
#pragma unroll
        for (int j = 0; j < 4; j++) s[i][j] = 0.f;

    // ---- Scores: 8 chunks of 32 keys ----
    const uint4* kH = (const uint4*)g_Khi;
    const uint4* kL = (const uint4*)g_Klo;
#pragma unroll
    for (int ch = 0; ch < 8; ch++) {
        __syncthreads();
#pragma unroll
        for (int i = tid; i < 512; i += 256) {
            const int mat = i >> 8, rr = (i & 255) >> 3, q4 = i & 7;
            const size_t gi = (size_t)(b * KANCH + ch * 32 + rr) * 128 + h * 8 + q4;
            uint4 v = mat ? kL[gi] : kH[gi];
            uint32_t* d = (mat ? kvl : kvh) + rr * 36 + q4 * 4;
            d[0] = v.x; d[1] = v.y; d[2] = v.z; d[3] = v.w;
        }
        __syncthreads();
#pragma unroll
        for (int nfl = 0; nfl < 4; nfl++) {
            float* cc = s[ch * 4 + nfl];
#pragma unroll
            for (int ks = 0; ks < 4; ks++) {
                const int rb = (nfl * 8 + g) * 36 + ks * 8 + t;
                const uint32_t b0h = kvh[rb], b1h = kvh[rb + 4];
                const uint32_t b0l = kvl[rb], b1l = kvl[rb + 4];
                mma_bf16(cc, qh[ks], b0h, b1h);
                mma_bf16(cc, qh[ks], b0l, b1l);
                mma_bf16(cc, ql[ks], b0h, b1h);
            }
        }
    }

    // ---- Softmax (rows g and g+8 of this warp's 16-row band) ----
    float mA = -1e30f, mB = -1e30f;
#pragma unroll
    for (int nf = 0; nf < 32; nf++) {
        mA = fmaxf(mA, fmaxf(s[nf][0], s[nf][1]));
        mB = fmaxf(mB, fmaxf(s[nf][2], s[nf][3]));
    }
    mA = fmaxf(mA, __shfl_xor_sync(0xffffffffu, mA, 1));
    mA = fmaxf(mA, __shfl_xor_sync(0xffffffffu, mA, 2));
    mB = fmaxf(mB, __shfl_xor_sync(0xffffffffu, mB, 1));
    mB = fmaxf(mB, __shfl_xor_sync(0xffffffffu, mB, 2));
    float lA = 0.f, lB = 0.f;
#pragma unroll
    for (int nf = 0; nf < 32; nf++) {
        s[nf][0] = __expf((s[nf][0] - mA) * SCALE); lA += s[nf][0];
        s[nf][1] = __expf((s[nf][1] - mA) * SCALE); lA += s[nf][1];
        s[nf][2] = __expf((s[nf][2] - mB) * SCALE); lB += s[nf][2];
        s[nf][3] = __expf((s[nf][3] - mB) * SCALE); lB += s[nf][3];
    }
    lA += __shfl_xor_sync(0xffffffffu, lA, 1);
    lA += __shfl_xor_sync(0xffffffffu, lA, 2);
    lB += __shfl_xor_sync(0xffffffffu, lB, 1);
    lB += __shfl_xor_sync(0xffffffffu, lB, 2);
    const float invA = 1.f / lA, invB = 1.f / lB;

    // ---- P·V: 8 chunks of 32 keys; V^T chunk = [64 d][16 u32], stride 20 ----
    float o[8][4];
#pragma unroll
    for (int i = 0; i < 8; i++)
#pragma unroll
        for (int j = 0; j < 4; j++) o[i][j] = 0.f;

    const uint4* vH = (const uint4*)g_Vthi;
    const uint4* vL = (const uint4*)g_Vtlo;
#pragma unroll
    for (int ch = 0; ch < 8; ch++) {
        __syncthreads();
#pragma unroll
        for (int i = tid; i < 512; i += 256) {
            const int mat = i >> 8, dd = (i & 255) >> 2, q4 = i & 3;
            const size_t gi = (size_t)((b * NHEAD + h) * HDIM + dd) * 32 + ch * 4 + q4;
            uint4 v = mat ? vL[gi] : vH[gi];
            uint32_t* d = (mat ? kvl : kvh) + dd * 20 + q4 * 4;
            d[0] = v.x; d[1] = v.y; d[2] = v.z; d[3] = v.w;
        }
        __syncthreads();
#pragma unroll
        for (int kk = 0; kk < 2; kk++) {
            const int j0 = ch * 4 + kk * 2;
            uint32_t ah[4], al[4];
            split2(s[j0][0],     s[j0][1],     ah[0], al[0]);
            split2(s[j0][2],     s[j0][3],     ah[1], al[1]);
            split2(s[j0 + 1][0], s[j0 + 1][1], ah[2], al[2]);
            split2(s[j0 + 1][2], s[j0 + 1][3], ah[3], al[3]);
#pragma unroll
            for (int nf = 0; nf < 8; nf++) {
                const int rb = (nf * 8 + g) * 20 + kk * 8 + t;
                const uint32_t b0h = kvh[rb], b1h = kvh[rb + 4];
                const uint32_t b0l = kvl[rb], b1l = kvl[rb + 4];
                mma_bf16(o[nf], ah, b0h, b1h);
                mma_bf16(o[nf], ah, b0l, b1l);
                mma_bf16(o[nf], al, b0h, b1h);
            }
        }
    }

    // ---- Epilogue: normalize, split hi/lo, store ctx ----
    const size_t rowA = (size_t)(b * NTOK + n0 + wr + g);
    const size_t rowB = rowA + 8;
    uint32_t* Hi = (uint32_t*)g_chi;
    uint32_t* Lo = (uint32_t*)g_clo;
#pragma unroll
    for (int nf = 0; nf < 8; nf++) {
        const int col = h * 64 + nf * 8 + t * 2;
        uint32_t h0, l0, h1, l1;
        split2(o[nf][0] * invA, o[nf][1] * invA, h0, l0);
        split2(o[nf][2] * invB, o[nf][3] * invB, h1, l1);
        Hi[rowA * 512 + col / 2] = h0;
        Lo[rowA * 512 + col / 2] = l0;
        Hi[rowB * 512 + col / 2] = h1;
        Lo[rowB * 512 + col / 2] = l1;
    }
}

// ---------------------------------------------------------------------------
// kernel_launch
// ---------------------------------------------------------------------------
extern "C" void kernel_launch(void* const* d_in, const int* in_sizes, int n_in,
                              void* d_out, int out_size)
{
    const float* x   = (const float*)d_in[0];
    const float* Wq  = (const float*)d_in[1];
    const float* bq  = (const float*)d_in[2];
    const float* Wk  = (const float*)d_in[3];
    const float* bk  = (const float*)d_in[4];
    const float* Wv  = (const float*)d_in[5];
    const float* bv  = (const float*)d_in[6];
    const float* Wqt = (const float*)d_in[7];
    const float* bqt = (const float*)d_in[8];
    const float* Wo  = (const float*)d_in[9];
    const float* bo  = (const float*)d_in[10];
    float* out = (float*)d_out;

    split_x_kernel<<<4096, 256>>>(x);
    wprep_kernel<<<dim3(32, 32, 5), dim3(32, 8)>>>(Wq, Wqt, Wk, Wv, Wo);

    qproj_kernel<<<dim3(8, 128), 256, GEMM_SMEM>>>(bq, bqt);
    kproj_kernel<<<dim3(8, 8),   256, GEMM_SMEM>>>(bk);
    vproj_kernel<<<dim3(8, 8),   256, GEMM_SMEM>>>(bv);

    attn_mma_kernel<<<dim3(NTOK / 128, NHEAD, BATCH), 256>>>();

    oproj_kernel<<<dim3(8, 128), 256, GEMM_SMEM>>>(bo, out);
}

// round 8
// speedup vs baseline: 4.5385x; 1.0869x over previous
#include <cuda_runtime.h>
#include <cuda_bf16.h>
#include <math.h>
#include <stdint.h>

// Problem constants
#define BATCH   4
#define NTOK    4096
#define DMODEL  1024
#define NHEAD   16
#define HDIM    64
#define KANCH   256
#define MROWS   (BATCH * NTOK)        // 16384
#define SCALE   0.125f

// ---------------------------------------------------------------------------
// Scratch (device globals). RULE: device symbols referenced ONLY from device
// code (host-shadow + GB300 ATS silently swallows host-passed symbol stores).
// ---------------------------------------------------------------------------
__device__ __align__(16) __nv_bfloat16 g_xhi[MROWS * DMODEL];
__device__ __align__(16) __nv_bfloat16 g_xlo[MROWS * DMODEL];
__device__ __align__(16) __nv_bfloat16 g_Qhi[MROWS * DMODEL];
__device__ __align__(16) __nv_bfloat16 g_Qlo[MROWS * DMODEL];
__device__ __align__(16) __nv_bfloat16 g_Khi[BATCH * KANCH * DMODEL];
__device__ __align__(16) __nv_bfloat16 g_Klo[BATCH * KANCH * DMODEL];
// V transposed per (b,h): [b][h][d][key]
__device__ __align__(16) __nv_bfloat16 g_Vthi[BATCH * NHEAD * HDIM * KANCH];
__device__ __align__(16) __nv_bfloat16 g_Vtlo[BATCH * NHEAD * HDIM * KANCH];
__device__ __align__(16) __nv_bfloat16 g_chi[MROWS * DMODEL];
__device__ __align__(16) __nv_bfloat16 g_clo[MROWS * DMODEL];
// Transposed+split weights: [N][K] K-major. 0=Wq 1=Wqt 2=Wk 3=Wv 4=Wo
__device__ __align__(16) __nv_bfloat16 g_Wh[5][DMODEL * DMODEL];
__device__ __align__(16) __nv_bfloat16 g_Wl[5][DMODEL * DMODEL];

// ---------------------------------------------------------------------------
// Primitives
// ---------------------------------------------------------------------------
__device__ __forceinline__ uint32_t smem_to_u32(const void* p) {
    uint32_t a;
    asm("{ .reg .u64 t; cvta.to.shared.u64 t, %1; cvt.u32.u64 %0, t; }" : "=r"(a) : "l"(p));
    return a;
}
#define CP16(d, s) \
    asm volatile("cp.async.cg.shared.global [%0], [%1], 16;" :: "r"(d), "l"(s))
#define CP_COMMIT() asm volatile("cp.async.commit_group;")

__device__ __forceinline__ void mma_bf16(float* c, const uint32_t* a,
                                         uint32_t b0, uint32_t b1) {
    asm volatile(
        "mma.sync.aligned.m16n8k16.row.col.f32.bf16.bf16.f32 "
        "{%0,%1,%2,%3}, {%4,%5,%6,%7}, {%8,%9}, {%0,%1,%2,%3};"
        : "+f"(c[0]), "+f"(c[1]), "+f"(c[2]), "+f"(c[3])
        : "r"(a[0]), "r"(a[1]), "r"(a[2]), "r"(a[3]), "r"(b0), "r"(b1));
}

__device__ __forceinline__ void split2(float v0, float v1, uint32_t& hi, uint32_t& lo) {
    __nv_bfloat16 h0 = __float2bfloat16(v0), h1 = __float2bfloat16(v1);
    __nv_bfloat162 hh; hh.x = h0; hh.y = h1;
    __nv_bfloat162 ll;
    ll.x = __float2bfloat16(v0 - __bfloat162float(h0));
    ll.y = __float2bfloat16(v1 - __bfloat162float(h1));
    hi = *reinterpret_cast<uint32_t*>(&hh);
    lo = *reinterpret_cast<uint32_t*>(&ll);
}

// 16B-chunk XOR swizzle on 32B rows (8 u32): conflict-free frag loads,
// 16B-aligned cp.async stores.  (row, ch∈{0,1}) -> u32 offset.
#define SWADDR(row, ch) ((((row) << 3)) + ((((ch) ^ (((row) >> 2) & 1))) << 2))

// ---------------------------------------------------------------------------
// bf16x3 GEMM mainloop: acc = A(128x1024) @ B^T(128x1024)
// 256 thr, 8 warps (4x2), warp tile 32x64, BK=16, 3-stage cp.async ring.
// smem: 3 stages x 4 mats x 128 rows x 8 u32 = 48 KB dynamic (no opt-in).
// One __syncthreads per chunk; issue-ahead 2.
// ---------------------------------------------------------------------------
#define GEMM_SMEM 49152

__device__ __forceinline__ void gemm_main(
    const __nv_bfloat16* __restrict__ Ahi, const __nv_bfloat16* __restrict__ Alo,
    const __nv_bfloat16* __restrict__ Bhi, const __nv_bfloat16* __restrict__ Blo,
    float acc[2][8][4])
{
    extern __shared__ uint32_t sm[];
    const int tid  = threadIdx.x;
    const int lane = tid & 31;
    const int wid  = tid >> 5;
    const int wm   = wid >> 1;
    const int wn   = wid & 1;
    const int g    = lane >> 2;
    const int t    = lane & 3;

#pragma unroll
    for (int i = 0; i < 2; i++)
#pragma unroll
        for (int j = 0; j < 8; j++)
#pragma unroll
            for (int k = 0; k < 4; k++) acc[i][j][k] = 0.f;

    const char* gp[4] = { (const char*)Ahi, (const char*)Alo,
                          (const char*)Bhi, (const char*)Blo };

    const int row = tid >> 1;
    const int ch  = tid & 1;
    const uint32_t swo = SWADDR(row, ch);               // u32 offset in mat
    const uint32_t sb  = smem_to_u32(sm);
    const size_t   gof = (size_t)row * 512 + ch * 4;    // u32 offset in gmem row

#define G_ISSUE(c) do {                                                        \
        const uint32_t _st = ((uint32_t)((c) % 3)) * 4096u;                    \
        const size_t _gb = (gof + (size_t)(c) * 8) << 2;                       \
        _Pragma("unroll")                                                      \
        for (int m = 0; m < 4; m++)                                            \
            CP16(sb + ((_st + m * 1024u + swo) << 2), gp[m] + _gb);            \
        CP_COMMIT();                                                           \
    } while (0)

    G_ISSUE(0);
    G_ISSUE(1);

    for (int c = 0; c < 64; c++) {
        // chunk c ready (issued 2 iters ago; <=1 newer group may be pending)
        if (c == 63) asm volatile("cp.async.wait_group 0;");
        else         asm volatile("cp.async.wait_group 1;");
        __syncthreads();          // data visible AND all warps done compute(c-1)
        if (c + 2 < 64) G_ISSUE(c + 2);   // safe: overwrites slot of chunk c-1

        const uint32_t* st = sm + (c % 3) * 4096;
        uint32_t aHi[2][4], aLo[2][4];
#pragma unroll
        for (int mf = 0; mf < 2; mf++) {
            const int rA0 = wm * 32 + mf * 16 + g;
            const int rA1 = rA0 + 8;
            aHi[mf][0] = st[SWADDR(rA0, 0) + t];
            aHi[mf][1] = st[SWADDR(rA1, 0) + t];
            aHi[mf][2] = st[SWADDR(rA0, 1) + t];
            aHi[mf][3] = st[SWADDR(rA1, 1) + t];
            aLo[mf][0] = st[1024 + SWADDR(rA0, 0) + t];
            aLo[mf][1] = st[1024 + SWADDR(rA1, 0) + t];
            aLo[mf][2] = st[1024 + SWADDR(rA0, 1) + t];
            aLo[mf][3] = st[1024 + SWADDR(rA1, 1) + t];
        }
#pragma unroll
        for (int nq = 0; nq < 4; nq++) {
#pragma unroll
            for (int hf = 0; hf < 2; hf++) {
                const int rB = wn * 64 + nq * 16 + hf * 8 + g;
                const uint32_t b0h = st[2048 + SWADDR(rB, 0) + t];
                const uint32_t b1h = st[2048 + SWADDR(rB, 1) + t];
                const uint32_t b0l = st[3072 + SWADDR(rB, 0) + t];
                const uint32_t b1l = st[3072 + SWADDR(rB, 1) + t];
                float* c0 = acc[0][nq * 2 + hf];
                float* c1 = acc[1][nq * 2 + hf];
                mma_bf16(c0, aHi[0], b0h, b1h);
                mma_bf16(c0, aHi[0], b0l, b1l);
                mma_bf16(c0, aLo[0], b0h, b1h);
                mma_bf16(c1, aHi[1], b0h, b1h);
                mma_bf16(c1, aHi[1], b0l, b1l);
                mma_bf16(c1, aLo[1], b0h, b1h);
            }
        }
    }
#undef G_ISSUE
}

// ---- Q projection: writes bf16 hi/lo directly ----
__global__ void __launch_bounds__(256, 2) qproj_kernel(
    const float* __restrict__ bq, const float* __restrict__ bqt)
{
    const int Mb = blockIdx.y * 128;
    const int Nb = blockIdx.x * 128;
    const bool anchor = (Mb % NTOK) < KANCH;
    const int w = anchor ? 0 : 1;
    float acc[2][8][4];
    gemm_main(g_xhi + (size_t)Mb * DMODEL, g_xlo + (size_t)Mb * DMODEL,
              g_Wh[w] + (size_t)Nb * DMODEL, g_Wl[w] + (size_t)Nb * DMODEL, acc);
    const float* bias = anchor ? bq : bqt;
    const int lane = threadIdx.x & 31, wid = threadIdx.x >> 5;
    const int wm = wid >> 1, wn = wid & 1, g = lane >> 2, t = lane & 3;
    uint32_t* Hi = (uint32_t*)g_Qhi;
    uint32_t* Lo = (uint32_t*)g_Qlo;
#pragma unroll
    for (int mf = 0; mf < 2; mf++)
#pragma unroll
        for (int nf = 0; nf < 8; nf++) {
            const int row = Mb + wm * 32 + mf * 16 + g;
            const int col = Nb + wn * 64 + nf * 8 + t * 2;
            const float bx = bias[col], by = bias[col + 1];
            uint32_t h0, l0, h1, l1;
            split2(acc[mf][nf][0] + bx, acc[mf][nf][1] + by, h0, l0);
            split2(acc[mf][nf][2] + bx, acc[mf][nf][3] + by, h1, l1);
            Hi[(size_t)row * 512 + col / 2] = h0;
            Lo[(size_t)row * 512 + col / 2] = l0;
            Hi[(size_t)(row + 8) * 512 + col / 2] = h1;
            Lo[(size_t)(row + 8) * 512 + col / 2] = l1;
        }
}

// ---- K/V projection over the 1024 anchor rows (merged; z selects) ----
__global__ void __launch_bounds__(256, 2) kvproj_kernel(
    const float* __restrict__ bk, const float* __restrict__ bv)
{
    const int Mt = blockIdx.y;
    const int arow = (Mt >> 1) * NTOK + (Mt & 1) * 128;
    const int Nb = blockIdx.x * 128;
    const int w = (blockIdx.z == 0) ? 2 : 3;
    float acc[2][8][4];
    gemm_main(g_xhi + (size_t)arow * DMODEL, g_xlo + (size_t)arow * DMODEL,
              g_Wh[w] + (size_t)Nb * DMODEL, g_Wl[w] + (size_t)Nb * DMODEL, acc);
    const int lane = threadIdx.x & 31, wid = threadIdx.x >> 5;
    const int wm = wid >> 1, wn = wid & 1, g = lane >> 2, t = lane & 3;
    if (blockIdx.z == 0) {
        uint32_t* Hi = (uint32_t*)g_Khi;
        uint32_t* Lo = (uint32_t*)g_Klo;
#pragma unroll
        for (int mf = 0; mf < 2; mf++)
#pragma unroll
            for (int nf = 0; nf < 8; nf++) {
                const int row = Mt * 128 + wm * 32 + mf * 16 + g;
                const int col = Nb + wn * 64 + nf * 8 + t * 2;
                const float bx = bk[col], by = bk[col + 1];
                uint32_t h0, l0, h1, l1;
                split2(acc[mf][nf][0] + bx, acc[mf][nf][1] + by, h0, l0);
                split2(acc[mf][nf][2] + bx, acc[mf][nf][3] + by, h1, l1);
                Hi[(size_t)row * 512 + col / 2] = h0;
                Lo[(size_t)row * 512 + col / 2] = l0;
                Hi[(size_t)(row + 8) * 512 + col / 2] = h1;
                Lo[(size_t)(row + 8) * 512 + col / 2] = l1;
            }
    } else {
#pragma unroll
        for (int mf = 0; mf < 2; mf++)
#pragma unroll
            for (int nf = 0; nf < 8; nf++) {
                const int col = Nb + wn * 64 + nf * 8 + t * 2;
                const int h = col >> 6, d = col & 63;
#pragma unroll
                for (int rr = 0; rr < 2; rr++) {
                    const int a = Mt * 128 + wm * 32 + mf * 16 + g + rr * 8;
                    const int b = a >> 8, tok = a & 255;
                    const float v0 = acc[mf][nf][rr * 2 + 0] + bv[col];
                    const float v1 = acc[mf][nf][rr * 2 + 1] + bv[col + 1];
                    const size_t i0 = ((size_t)((b * NHEAD + h) * HDIM + d)) * KANCH + tok;
                    __nv_bfloat16 h0 = __float2bfloat16(v0);
                    __nv_bfloat16 h1 = __float2bfloat16(v1);
                    g_Vthi[i0] = h0;
                    g_Vtlo[i0] = __float2bfloat16(v0 - __bfloat162float(h0));
                    g_Vthi[i0 + KANCH] = h1;
                    g_Vtlo[i0 + KANCH] = __float2bfloat16(v1 - __bfloat162float(h1));
                }
            }
    }
}

// ---- Output projection: ctx(hi/lo) @ Wo + bo -> fp32 out ----
__global__ void __launch_bounds__(256, 2) oproj_kernel(
    const float* __restrict__ bo, float* __restrict__ out)
{
    const int Mb = blockIdx.y * 128;
    const int Nb = blockIdx.x * 128;
    float acc[2][8][4];
    gemm_main(g_chi + (size_t)Mb * DMODEL, g_clo + (size_t)Mb * DMODEL,
              g_Wh[4] + (size_t)Nb * DMODEL, g_Wl[4] + (size_t)Nb * DMODEL, acc);
    const int lane = threadIdx.x & 31, wid = threadIdx.x >> 5;
    const int wm = wid >> 1, wn = wid & 1, g = lane >> 2, t = lane & 3;
#pragma unroll
    for (int mf = 0; mf < 2; mf++)
#pragma unroll
        for (int nf = 0; nf < 8; nf++) {
            const int row = Mb + wm * 32 + mf * 16 + g;
            const int col = Nb + wn * 64 + nf * 8 + t * 2;
            const float bx = bo[col], by = bo[col + 1];
            float2 v0 = { acc[mf][nf][0] + bx, acc[mf][nf][1] + by };
            float2 v1 = { acc[mf][nf][2] + bx, acc[mf][nf][3] + by };
            *reinterpret_cast<float2*>(out + (size_t)row * DMODEL + col) = v0;
            *reinterpret_cast<float2*>(out + (size_t)(row + 8) * DMODEL + col) = v1;
        }
}

// ---------------------------------------------------------------------------
// Split x fp32 -> g_xhi/g_xlo (device symbols only)
// ---------------------------------------------------------------------------
__global__ void __launch_bounds__(256) split_x_kernel(const float* __restrict__ in)
{
    const int n4 = MROWS * DMODEL / 4;
    for (int i = blockIdx.x * blockDim.x + threadIdx.x; i < n4; i += gridDim.x * blockDim.x) {
        float4 v = reinterpret_cast<const float4*>(in)[i];
        uint32_t hA, lA, hB, lB;
        split2(v.x, v.y, hA, lA);
        split2(v.z, v.w, hB, lB);
        reinterpret_cast<uint32_t*>(g_xhi)[i * 2 + 0] = hA;
        reinterpret_cast<uint32_t*>(g_xhi)[i * 2 + 1] = hB;
        reinterpret_cast<uint32_t*>(g_xlo)[i * 2 + 0] = lA;
        reinterpret_cast<uint32_t*>(g_xlo)[i * 2 + 1] = lB;
    }
}

// ---------------------------------------------------------------------------
// Transpose + split weights: src [K][N] -> g_Wh/g_Wl [N][K]
// ---------------------------------------------------------------------------
__global__ void __launch_bounds__(256) wprep_kernel(
    const float* __restrict__ Wq, const float* __restrict__ Wqt,
    const float* __restrict__ Wk, const float* __restrict__ Wv,
    const float* __restrict__ Wo)
{
    __shared__ float tbuf[32][33];
    const float* src;
    switch (blockIdx.z) {
        case 0: src = Wq;  break;
        case 1: src = Wqt; break;
        case 2: src = Wk;  break;
        case 3: src = Wv;  break;
        default: src = Wo; break;
    }
    __nv_bfloat16* dh = g_Wh[blockIdx.z];
    __nv_bfloat16* dl = g_Wl[blockIdx.z];
    const int n0 = blockIdx.x * 32, k0 = blockIdx.y * 32;
    for (int i = threadIdx.y; i < 32; i += 8)
        tbuf[i][threadIdx.x] = src[(size_t)(k0 + i) * DMODEL + n0 + threadIdx.x];
    __syncthreads();
    for (int i = threadIdx.y; i < 32; i += 8) {
        float v = tbuf[threadIdx.x][i];
        __nv_bfloat16 h = __float2bfloat16(v);
        size_t idx = (size_t)(n0 + i) * DMODEL + k0 + threadIdx.x;
        dh[idx] = h;
        dl[idx] = __float2bfloat16(v - __bfloat162float(h));
    }
}

// ---------------------------------------------------------------------------
// Tensor-core attention: CTA = 128 Q rows x one (b,h). 8 warps, warp = 16 rows.
// S[16x256] in accum regs (bf16x3 Q·K), full softmax (K=256, one pass),
// P·V with register-resident P hi/lo (bf16x3). Writes ctx hi/lo.
// ---------------------------------------------------------------------------
__global__ void __launch_bounds__(256) attn_mma_kernel()
{
    __shared__ uint32_t qsh[128 * 36], qsl[128 * 36];   // Q tile, stride 36
    __shared__ uint32_t kvh[1280], kvl[1280];           // K chunk (36) / V chunk (20)

    const int b = blockIdx.z, h = blockIdx.y;
    const int n0 = blockIdx.x * 128;
    const int tid = threadIdx.x, lane = tid & 31, wid = tid >> 5;
    const int g = lane >> 2, t = lane & 3;
    const int wr = wid * 16;

    // Q tile: 128 rows x 64d, hi+lo (2048 uint4)
    {
        const uint4* sH = (const uint4*)g_Qhi;
        const uint4* sL = (const uint4*)g_Qlo;
#pragma unroll
        for (int i = tid; i < 2048; i += 256) {
            const int mat = i >> 10, rr = (i & 1023) >> 3, q4 = i & 7;
            const size_t gi = (size_t)(b * NTOK + n0 + rr) * 128 + h * 8 + q4;
            uint4 v = mat ? sL[gi] : sH[gi];
            uint32_t* d = (mat ? qsl : qsh) + rr * 36 + q4 * 4;
            d[0] = v.x; d[1] = v.y; d[2] = v.z; d[3] = v.w;
        }
    }
    __syncthreads();

    // Persistent Q fragments
    uint32_t qh[4][4], ql[4][4];
#pragma unroll
    for (int ks = 0; ks < 4; ks++) {
        const int rA0 = (wr + g) * 36 + ks * 8 + t;
        const int rA1 = (wr + 8 + g) * 36 + ks * 8 + t;
        qh[ks][0] = qsh[rA0]; qh[ks][1] = qsh[rA1];
        qh[ks][2] = qsh[rA0 + 4]; qh[ks][3] = qsh[rA1 + 4];
        ql[ks][0] = qsl[rA0]; ql[ks][1] = qsl[rA1];
        ql[ks][2] = qsl[rA0 + 4]; ql[ks][3] = qsl[rA1 + 4];
    }

    float s[32][4];
#pragma unroll
    for (int i = 0; i < 32; i++)
#pragma unroll
        for (int j = 0; j < 4; j++) s[i][j] = 0.f;

    // ---- Scores: 8 chunks of 32 keys ----
    const uint4* kH = (const uint4*)g_Khi;
    const uint4* kL = (const uint4*)g_Klo;
#pragma unroll
    for (int ch = 0; ch < 8; ch++) {
        __syncthreads();
#pragma unroll
        for (int i = tid; i < 512; i += 256) {
            const int mat = i >> 8, rr = (i & 255) >> 3, q4 = i & 7;
            const size_t gi = (size_t)(b * KANCH + ch * 32 + rr) * 128 + h * 8 + q4;
            uint4 v = mat ? kL[gi] : kH[gi];
            uint32_t* d = (mat ? kvl : kvh) + rr * 36 + q4 * 4;
            d[0] = v.x; d[1] = v.y; d[2] = v.z; d[3] = v.w;
        }
        __syncthreads();
#pragma unroll
        for (int nfl = 0; nfl < 4; nfl++) {
            float* cc = s[ch * 4 + nfl];
#pragma unroll
            for (int ks = 0; ks < 4; ks++) {
                const int rb = (nfl * 8 + g) * 36 + ks * 8 + t;
                const uint32_t b0h = kvh[rb], b1h = kvh[rb + 4];
                const uint32_t b0l = kvl[rb], b1l = kvl[rb + 4];
                mma_bf16(cc, qh[ks], b0h, b1h);
                mma_bf16(cc, qh[ks], b0l, b1l);
                mma_bf16(cc, ql[ks], b0h, b1h);
            }
        }
    }

    // ---- Softmax ----
    float mA = -1e30f, mB = -1e30f;
#pragma unroll
    for (int nf = 0; nf < 32; nf++) {
        mA = fmaxf(mA, fmaxf(s[nf][0], s[nf][1]));
        mB = fmaxf(mB, fmaxf(s[nf][2], s[nf][3]));
    }
    mA = fmaxf(mA, __shfl_xor_sync(0xffffffffu, mA, 1));
    mA = fmaxf(mA, __shfl_xor_sync(0xffffffffu, mA, 2));
    mB = fmaxf(mB, __shfl_xor_sync(0xffffffffu, mB, 1));
    mB = fmaxf(mB, __shfl_xor_sync(0xffffffffu, mB, 2));
    float lA = 0.f, lB = 0.f;
#pragma unroll
    for (int nf = 0; nf < 32; nf++) {
        s[nf][0] = __expf((s[nf][0] - mA) * SCALE); lA += s[nf][0];
        s[nf][1] = __expf((s[nf][1] - mA) * SCALE); lA += s[nf][1];
        s[nf][2] = __expf((s[nf][2] - mB) * SCALE); lB += s[nf][2];
        s[nf][3] = __expf((s[nf][3] - mB) * SCALE); lB += s[nf][3];
    }
    lA += __shfl_xor_sync(0xffffffffu, lA, 1);
    lA += __shfl_xor_sync(0xffffffffu, lA, 2);
    lB += __shfl_xor_sync(0xffffffffu, lB, 1);
    lB += __shfl_xor_sync(0xffffffffu, lB, 2);
    const float invA = 1.f / lA, invB = 1.f / lB;

    // ---- P·V ----
    float o[8][4];
#pragma unroll
    for (int i = 0; i < 8; i++)
#pragma unroll
        for (int j = 0; j < 4; j++) o[i][j] = 0.f;

    const uint4* vH = (const uint4*)g_Vthi;
    const uint4* vL = (const uint4*)g_Vtlo;
#pragma unroll
    for (int ch = 0; ch < 8; ch++) {
        __syncthreads();
#pragma unroll
        for (int i = tid; i < 512; i += 256) {
            const int mat = i >> 8, dd = (i & 255) >> 2, q4 = i & 3;
            const size_t gi = (size_t)((b * NHEAD + h) * HDIM + dd) * 32 + ch * 4 + q4;
            uint4 v = mat ? vL[gi] : vH[gi];
            uint32_t* d = (mat ? kvl : kvh) + dd * 20 + q4 * 4;
            d[0] = v.x; d[1] = v.y; d[2] = v.z; d[3] = v.w;
        }
        __syncthreads();
#pragma unroll
        for (int kk = 0; kk < 2; kk++) {
            const int j0 = ch * 4 + kk * 2;
            uint32_t ah[4], al[4];
            split2(s[j0][0],     s[j0][1],     ah[0], al[0]);
            split2(s[j0][2],     s[j0][3],     ah[1], al[1]);
            split2(s[j0 + 1][0], s[j0 + 1][1], ah[2], al[2]);
            split2(s[j0 + 1][2], s[j0 + 1][3], ah[3], al[3]);
#pragma unroll
            for (int nf = 0; nf < 8; nf++) {
                const int rb = (nf * 8 + g) * 20 + kk * 8 + t;
                const uint32_t b0h = kvh[rb], b1h = kvh[rb + 4];
                const uint32_t b0l = kvl[rb], b1l = kvl[rb + 4];
                mma_bf16(o[nf], ah, b0h, b1h);
                mma_bf16(o[nf], ah, b0l, b1l);
                mma_bf16(o[nf], al, b0h, b1h);
            }
        }
    }

    // ---- Epilogue: normalize, split hi/lo, store ctx ----
    const size_t rowA = (size_t)(b * NTOK + n0 + wr + g);
    const size_t rowB = rowA + 8;
    uint32_t* Hi = (uint32_t*)g_chi;
    uint32_t* Lo = (uint32_t*)g_clo;
#pragma unroll
    for (int nf = 0; nf < 8; nf++) {
        const int col = h * 64 + nf * 8 + t * 2;
        uint32_t h0, l0, h1, l1;
        split2(o[nf][0] * invA, o[nf][1] * invA, h0, l0);
        split2(o[nf][2] * invB, o[nf][3] * invB, h1, l1);
        Hi[rowA * 512 + col / 2] = h0;
        Lo[rowA * 512 + col / 2] = l0;
        Hi[rowB * 512 + col / 2] = h1;
        Lo[rowB * 512 + col / 2] = l1;
    }
}

// ---------------------------------------------------------------------------
// kernel_launch
// ---------------------------------------------------------------------------
extern "C" void kernel_launch(void* const* d_in, const int* in_sizes, int n_in,
                              void* d_out, int out_size)
{
    const float* x   = (const float*)d_in[0];
    const float* Wq  = (const float*)d_in[1];
    const float* bq  = (const float*)d_in[2];
    const float* Wk  = (const float*)d_in[3];
    const float* bk  = (const float*)d_in[4];
    const float* Wv  = (const float*)d_in[5];
    const float* bv  = (const float*)d_in[6];
    const float* Wqt = (const float*)d_in[7];
    const float* bqt = (const float*)d_in[8];
    const float* Wo  = (const float*)d_in[9];
    const float* bo  = (const float*)d_in[10];
    float* out = (float*)d_out;

    split_x_kernel<<<4096, 256>>>(x);
    wprep_kernel<<<dim3(32, 32, 5), dim3(32, 8)>>>(Wq, Wqt, Wk, Wv, Wo);

    qproj_kernel<<<dim3(8, 128), 256, GEMM_SMEM>>>(bq, bqt);
    kvproj_kernel<<<dim3(8, 8, 2), 256, GEMM_SMEM>>>(bk, bv);

    attn_mma_kernel<<<dim3(NTOK / 128, NHEAD, BATCH), 256>>>();

    oproj_kernel<<<dim3(8, 128), 256, GEMM_SMEM>>>(bo, out);
}